// round 1
// baseline (speedup 1.0000x reference)
#include <cuda_runtime.h>
#include <math.h>

// Problem constants (fixed by setup_inputs)
#define D      256
#define KCODES 2048
#define NROWS  65536          // 16 * 4096
#define BM     64             // rows per block in argmin kernel
#define BN     64             // code tile
#define NT     256            // threads per block (16x16)
#define ZP     68             // padded smem row length (floats)

// Scratch (no device mallocs allowed)
__device__ float g_enorm[KCODES];    // ||e_k||^2 / 2
__device__ int   g_index[NROWS];     // argmin indices
__device__ float g_counts[KCODES];   // histogram
__device__ float g_loss_sum;         // sum of (z_q - z)^2

// ---------------------------------------------------------------------------
// Kernel 1: per-code half-squared-norms + zero counts/loss.
// Launch <<<256,256>>> -> 2048 warps, one warp per code row.
// ---------------------------------------------------------------------------
__global__ void enorm_init_kernel(const float* __restrict__ e) {
    int tid = blockIdx.x * blockDim.x + threadIdx.x;
    int w = tid >> 5, l = tid & 31;
    if (w < KCODES) {
        const float* row = e + (size_t)w * D;
        float s0 = 0.f, s1 = 0.f;
        #pragma unroll
        for (int d = 0; d < D; d += 64) { float a = row[d + l];      s0 += a * a; }
        #pragma unroll
        for (int d = 0; d < D; d += 64) { float a = row[d + 32 + l]; s1 += a * a; }
        float s = s0 + s1;
        #pragma unroll
        for (int o = 16; o; o >>= 1) s += __shfl_xor_sync(0xffffffffu, s, o);
        if (l == 0) g_enorm[w] = 0.5f * s;
    }
    if (tid < KCODES) g_counts[tid] = 0.f;
    if (tid == 0) g_loss_sum = 0.f;
}

// ---------------------------------------------------------------------------
// Kernel 2: fused distance-GEMM + argmin.
// Block = 64 z-rows vs all 2048 codes. argmin of ||z-e||^2 over codes is
// equivalent to argmin of (||e||^2/2 - z.e); ||z||^2 is row-constant.
// Smem: Zs[d][64] and Es[d][64] (d-major, padded). 16x16 threads, each
// computing a 4x4 micro-tile of dots with running (min, idx).
// ---------------------------------------------------------------------------
__global__ void argmin_kernel(const float* __restrict__ z,
                              const float* __restrict__ e,
                              float* __restrict__ out_idx) {
    extern __shared__ float smem[];
    float* Zs = smem;              // [D][ZP]
    float* Es = smem + D * ZP;     // [D][ZP]

    const int tid = threadIdx.x;
    const int tx = tid & 15, ty = tid >> 4;
    const int tx4 = tx * 4, ty4 = ty * 4;
    const int row0 = blockIdx.x * BM;

    // Load Z tile, transposed to d-major.
    {
        const float4* zg = (const float4*)(z + (size_t)row0 * D);
        for (int i = tid; i < BM * (D / 4); i += NT) {
            int r = i >> 6;          // D/4 == 64
            int c4 = i & 63;
            float4 v = zg[(size_t)r * 64 + c4];
            int d = c4 * 4;
            Zs[(d + 0) * ZP + r] = v.x;
            Zs[(d + 1) * ZP + r] = v.y;
            Zs[(d + 2) * ZP + r] = v.z;
            Zs[(d + 3) * ZP + r] = v.w;
        }
    }

    float bestv[4];
    int   besti[4];
    #pragma unroll
    for (int i = 0; i < 4; ++i) { bestv[i] = 3.4e38f; besti[i] = 0; }

    for (int nt = 0; nt < KCODES / BN; ++nt) {
        __syncthreads();   // previous tile's compute done before overwrite
        // Load E tile, transposed to d-major.
        {
            const float4* eg = (const float4*)(e + (size_t)nt * BN * D);
            for (int i = tid; i < BN * (D / 4); i += NT) {
                int r = i >> 6;
                int c4 = i & 63;
                float4 v = eg[(size_t)r * 64 + c4];
                int d = c4 * 4;
                Es[(d + 0) * ZP + r] = v.x;
                Es[(d + 1) * ZP + r] = v.y;
                Es[(d + 2) * ZP + r] = v.z;
                Es[(d + 3) * ZP + r] = v.w;
            }
        }
        __syncthreads();

        float acc[4][4];
        #pragma unroll
        for (int i = 0; i < 4; ++i)
            #pragma unroll
            for (int j = 0; j < 4; ++j) acc[i][j] = 0.f;

        // Software-pipelined dot accumulation over D.
        float4 zA = *(const float4*)(Zs + ty4);
        float4 eA = *(const float4*)(Es + tx4);
        #pragma unroll 8
        for (int d = 0; d < D; ++d) {
            float4 zN, eN;
            if (d + 1 < D) {
                zN = *(const float4*)(Zs + (d + 1) * ZP + ty4);
                eN = *(const float4*)(Es + (d + 1) * ZP + tx4);
            }
            float za[4] = {zA.x, zA.y, zA.z, zA.w};
            float ea[4] = {eA.x, eA.y, eA.z, eA.w};
            #pragma unroll
            for (int i = 0; i < 4; ++i)
                #pragma unroll
                for (int j = 0; j < 4; ++j)
                    acc[i][j] += za[i] * ea[j];
            zA = zN; eA = eN;
        }

        // score = ||e||^2/2 - z.e ; strict < keeps earliest (smallest) index.
        #pragma unroll
        for (int j = 0; j < 4; ++j) {
            int cidx = nt * BN + tx4 + j;
            float enh = g_enorm[cidx];
            #pragma unroll
            for (int i = 0; i < 4; ++i) {
                float s = enh - acc[i][j];
                if (s < bestv[i]) { bestv[i] = s; besti[i] = cidx; }
            }
        }
    }

    // Cross-thread reduction per row (16 tx lanes own interleaved columns).
    __syncthreads();
    float* sv = smem;                       // [BM][16]
    int*   si = (int*)(smem + BM * 16);     // [BM][16]
    #pragma unroll
    for (int i = 0; i < 4; ++i) {
        sv[(ty4 + i) * 16 + tx] = bestv[i];
        si[(ty4 + i) * 16 + tx] = besti[i];
    }
    __syncthreads();
    if (tid < BM) {
        float bv = sv[tid * 16];
        int   bi = si[tid * 16];
        #pragma unroll
        for (int t = 1; t < 16; ++t) {
            float v = sv[tid * 16 + t];
            int  ii = si[tid * 16 + t];
            if (v < bv || (v == bv && ii < bi)) { bv = v; bi = ii; }
        }
        int row = row0 + tid;
        g_index[row] = bi;
        out_idx[row] = (float)bi;               // indices, cast to output dtype
        atomicAdd(&g_counts[bi], 1.0f);
    }
}

// ---------------------------------------------------------------------------
// Kernel 3: gather z_q (== z_q_st numerically) + commitment-loss partials.
// One float4 per thread; exactly N*D/4 threads.
// ---------------------------------------------------------------------------
__global__ void gather_loss_kernel(const float* __restrict__ z,
                                   const float* __restrict__ e,
                                   float* __restrict__ out) {
    int i = blockIdx.x * blockDim.x + threadIdx.x;   // float4 index
    int row = i >> 6;                                 // D/4 == 64
    int c4 = i & 63;
    int idx = g_index[row];
    float4 ev = ((const float4*)e)[(size_t)idx * 64 + c4];
    float4 zv = ((const float4*)z)[i];
    ((float4*)out)[i] = ev;
    float dx = ev.x - zv.x, dy = ev.y - zv.y;
    float dz = ev.z - zv.z, dw = ev.w - zv.w;
    float ls = dx * dx + dy * dy + dz * dz + dw * dw;

    __shared__ float red[32];
    #pragma unroll
    for (int o = 16; o; o >>= 1) ls += __shfl_xor_sync(0xffffffffu, ls, o);
    int l = threadIdx.x & 31, w = threadIdx.x >> 5;
    if (l == 0) red[w] = ls;
    __syncthreads();
    if (w == 0) {
        float v = (l < ((int)blockDim.x >> 5)) ? red[l] : 0.f;
        #pragma unroll
        for (int o = 16; o; o >>= 1) v += __shfl_xor_sync(0xffffffffu, v, o);
        if (l == 0) atomicAdd(&g_loss_sum, v);
    }
}

// ---------------------------------------------------------------------------
// Kernel 4: loss scalar + perplexity.
// ---------------------------------------------------------------------------
__global__ void finalize_kernel(float* __restrict__ out) {
    const float invN = 1.0f / (float)NROWS;
    float s = 0.f;
    for (int k = threadIdx.x; k < KCODES; k += blockDim.x) {
        float p = g_counts[k] * invN;
        s += p * logf(p + 1e-10f);
    }
    __shared__ float red[32];
    #pragma unroll
    for (int o = 16; o; o >>= 1) s += __shfl_xor_sync(0xffffffffu, s, o);
    int l = threadIdx.x & 31, w = threadIdx.x >> 5;
    if (l == 0) red[w] = s;
    __syncthreads();
    if (w == 0) {
        float v = (l < ((int)blockDim.x >> 5)) ? red[l] : 0.f;
        #pragma unroll
        for (int o = 16; o; o >>= 1) v += __shfl_xor_sync(0xffffffffu, v, o);
        if (l == 0) {
            const size_t NZ = (size_t)NROWS * D;
            out[NZ] = 0.25f * g_loss_sum / (float)NZ;              // loss
            out[NZ + 1 + NROWS] = expf(-v);                        // perplexity
        }
    }
}

// ---------------------------------------------------------------------------
// Output layout (flattened tuple, all float32):
//   [0, N*D)            z_q_st
//   [N*D]               loss
//   [N*D+1, N*D+1+N)    encoding_indices (cast to float)
//   [N*D+1+N]           perplexity
// ---------------------------------------------------------------------------
extern "C" void kernel_launch(void* const* d_in, const int* in_sizes, int n_in,
                              void* d_out, int out_size) {
    const float* z = (const float*)d_in[0];
    const float* e = (const float*)d_in[1];
    float* out = (float*)d_out;

    const int smem_bytes = 2 * D * ZP * (int)sizeof(float);   // 139264
    cudaFuncSetAttribute(argmin_kernel,
                         cudaFuncAttributeMaxDynamicSharedMemorySize, smem_bytes);

    enorm_init_kernel<<<256, 256>>>(e);
    argmin_kernel<<<NROWS / BM, NT, smem_bytes>>>(z, e, out + (size_t)NROWS * D + 1);
    gather_loss_kernel<<<(NROWS * (D / 4)) / 256, 256>>>(z, e, out);
    finalize_kernel<<<1, 256>>>(out);
}

// round 5
// speedup vs baseline: 2.4737x; 2.4737x over previous
#include <cuda_runtime.h>
#include <cuda_bf16.h>
#include <math.h>
#include <cstdint>

// ---------------------------------------------------------------------------
// Problem constants
// ---------------------------------------------------------------------------
#define DIM     256
#define KCODES  2048
#define NROWS   65536
#define BM      128            // z rows per CTA
#define BN      128            // codes per tile
#define NCHUNK  12             // B chunks per tile: {h,m,l} x 4 quarters of 64
#define NTILES  16             // KCODES / BN
#define NSTEPS  (NTILES * NCHUNK)   // 192

#define A_CHUNK_BYTES 16384    // BM * 64 * 2
#define A_BYTES       (NCHUNK * A_CHUNK_BYTES)   // 196608 (12 chunks: h,m,l x4)
#define B_CHUNK_BYTES 16384    // BN * 64 * 2
#define SMEM_BYTES    (A_BYTES + 2 * B_CHUNK_BYTES)   // 229376

// ---------------------------------------------------------------------------
// Device scratch (static: no runtime allocation)
// ---------------------------------------------------------------------------
__device__ float g_enorm[KCODES];
__device__ int   g_index[NROWS];
__device__ float g_counts[KCODES];
__device__ float g_loss_sum;
__device__ __align__(16) __nv_bfloat16 g_es[KCODES * 768];            // 3 MB
__device__ __align__(16) __nv_bfloat16 g_zs[(size_t)NROWS * 768];     // 96 MB

// ---------------------------------------------------------------------------
// PTX helpers (sm_80-class features only: work on plain sm_103 target)
// ---------------------------------------------------------------------------
__device__ __forceinline__ uint32_t smem_u32(const void* p) {
    uint32_t a;
    asm("{ .reg .u64 t; cvta.to.shared.u64 t, %1; cvt.u32.u64 %0, t; }"
        : "=r"(a) : "l"(p));
    return a;
}
__device__ __forceinline__ void cp16(uint32_t dst, const void* src) {
    asm volatile("cp.async.cg.shared.global [%0], [%1], 16;" :: "r"(dst), "l"(src));
}
#define CP_COMMIT() asm volatile("cp.async.commit_group;" ::: "memory")
#define CP_WAIT0()  asm volatile("cp.async.wait_group 0;" ::: "memory")

#define LDSM_X4(r, addr) \
    asm volatile("ldmatrix.sync.aligned.m8n8.x4.shared.b16 {%0,%1,%2,%3}, [%4];" \
        : "=r"((r)[0]), "=r"((r)[1]), "=r"((r)[2]), "=r"((r)[3]) : "r"(addr))

#define LDSM_X4B(r0, r1, r2, r3, addr) \
    asm volatile("ldmatrix.sync.aligned.m8n8.x4.shared.b16 {%0,%1,%2,%3}, [%4];" \
        : "=r"(r0), "=r"(r1), "=r"(r2), "=r"(r3) : "r"(addr))

#define MMA16816(d, a, b) \
    asm volatile("mma.sync.aligned.m16n8k16.row.col.f32.bf16.bf16.f32 " \
        "{%0,%1,%2,%3}, {%4,%5,%6,%7}, {%8,%9}, {%0,%1,%2,%3};" \
        : "+f"((d)[0]), "+f"((d)[1]), "+f"((d)[2]), "+f"((d)[3]) \
        : "r"((a)[0]), "r"((a)[1]), "r"((a)[2]), "r"((a)[3]), \
          "r"((b)[0]), "r"((b)[1]))

// ---------------------------------------------------------------------------
// bf16x3 split
// ---------------------------------------------------------------------------
__device__ __forceinline__ void split3(float v, __nv_bfloat16& h, __nv_bfloat16& m,
                                       __nv_bfloat16& l) {
    h = __float2bfloat16(v);
    float r = v - __bfloat162float(h);
    m = __float2bfloat16(r);
    l = __float2bfloat16(r - __bfloat162float(m));
}
__device__ __forceinline__ uint32_t pack2(__nv_bfloat16 lo, __nv_bfloat16 hi) {
    return ((uint32_t)__bfloat16_as_ushort(hi) << 16) | (uint32_t)__bfloat16_as_ushort(lo);
}

// ---------------------------------------------------------------------------
// Prep 1: z -> g_zs (split layout per row: [h(256)|m(256)|l(256)] bf16)
// ---------------------------------------------------------------------------
__global__ void prep_z_kernel(const float* __restrict__ z) {
    int i = blockIdx.x * blockDim.x + threadIdx.x;   // 0 .. NROWS*64-1
    int row = i >> 6;
    int c4 = i & 63;
    float4 v = ((const float4*)z)[i];
    float vv[4] = {v.x, v.y, v.z, v.w};
    uint32_t p[3][2];
    #pragma unroll
    for (int j = 0; j < 2; ++j) {
        __nv_bfloat16 h0, m0, l0, h1, m1, l1;
        split3(vv[2 * j], h0, m0, l0);
        split3(vv[2 * j + 1], h1, m1, l1);
        p[0][j] = pack2(h0, h1); p[1][j] = pack2(m0, m1); p[2][j] = pack2(l0, l1);
    }
    uint2* dst = (uint2*)g_zs;
    size_t base = (size_t)row * 192 + c4;            // uint2 units (8B)
    #pragma unroll
    for (int s = 0; s < 3; ++s)
        dst[base + s * 64] = make_uint2(p[s][0], p[s][1]);
}

// ---------------------------------------------------------------------------
// Prep 2: e -> g_es splits + enorm + zero counts/loss. One warp per code.
// ---------------------------------------------------------------------------
__global__ void prep_e_kernel(const float* __restrict__ e) {
    int t = blockIdx.x * blockDim.x + threadIdx.x;
    int w = t >> 5, l = t & 31;
    if (w < KCODES) {
        const float4* row = (const float4*)(e + (size_t)w * DIM);
        float4 a = row[2 * l], b = row[2 * l + 1];
        float vv[8] = {a.x, a.y, a.z, a.w, b.x, b.y, b.z, b.w};
        float s = 0.f;
        uint32_t ph[4], pm[4], pl[4];
        #pragma unroll
        for (int j = 0; j < 4; ++j) {
            float v0 = vv[2 * j], v1 = vv[2 * j + 1];
            s += v0 * v0 + v1 * v1;
            __nv_bfloat16 h0, m0, l0, h1, m1, l1;
            split3(v0, h0, m0, l0);
            split3(v1, h1, m1, l1);
            ph[j] = pack2(h0, h1); pm[j] = pack2(m0, m1); pl[j] = pack2(l0, l1);
        }
        uint4* dst = (uint4*)g_es;
        size_t base = (size_t)w * 96 + l;            // uint4 units (16B)
        dst[base]      = *(uint4*)ph;
        dst[base + 32] = *(uint4*)pm;
        dst[base + 64] = *(uint4*)pl;
        #pragma unroll
        for (int o = 16; o; o >>= 1) s += __shfl_xor_sync(0xffffffffu, s, o);
        if (l == 0) { g_enorm[w] = 0.5f * s; g_counts[w] = 0.f; }
    }
    if (t == 0) g_loss_sum = 0.f;
}

// ---------------------------------------------------------------------------
// B tile fill: 128 codes x 64 k (bf16) of split E into swizzled smem.
// step s: tile = s/12, chunk = s%12 (h0..h3, m0..m3, l0..l3)
// ---------------------------------------------------------------------------
__device__ __forceinline__ void fill_B(uint32_t sB, int step) {
    int tile = step / NCHUNK, chunk = step % NCHUNK, buf = step & 1;
    const char* src0 = (const char*)g_es + (size_t)tile * BN * 1536 + chunk * 128;
    uint32_t d0 = sB + buf * B_CHUNK_BYTES;
    #pragma unroll
    for (int o = 0; o < 8; ++o) {
        int idx = threadIdx.x + o * 128;             // 0..1023
        int row = idx >> 3, seg = idx & 7;
        uint32_t dst = d0 + row * 128 + (((uint32_t)(seg ^ (row & 7))) << 4);
        cp16(dst, src0 + (size_t)row * 1536 + seg * 16);
    }
}

// ---------------------------------------------------------------------------
// One B-chunk pass: load B frags once per ks, MMA against NPART A splits.
// A chunk = asplit*4 + kq. acc accumulates across the whole tile.
// ---------------------------------------------------------------------------
template <int NPART>
__device__ __forceinline__ void chunk_pass(
    uint32_t sA, uint32_t bBase, int kq, int lane,
    float (&acc)[4][8][4], int wm, int wn)
{
    const int m = lane >> 3, r8 = lane & 7;
    #pragma unroll
    for (int ks = 0; ks < 4; ++ks) {
        // B fragments (non-trans; smem [code][k], k contiguous):
        uint32_t b[8][2];
        #pragma unroll
        for (int nb = 0; nb < 4; ++nb) {
            int code = wn + nb * 16 + ((m >> 1) << 3) + r8;
            int kseg = ks * 2 + (m & 1);
            uint32_t addr = bBase + code * 128 +
                            (((uint32_t)(kseg ^ (code & 7))) << 4);
            LDSM_X4B(b[2 * nb][0], b[2 * nb][1],
                     b[2 * nb + 1][0], b[2 * nb + 1][1], addr);
        }
        #pragma unroll
        for (int p = 0; p < NPART; ++p) {
            const uint32_t aBase = sA + (uint32_t)(p * 4 + kq) * A_CHUNK_BYTES;
            uint32_t a[4][4];
            #pragma unroll
            for (int mi = 0; mi < 4; ++mi) {
                int row = wm + mi * 16 + r8 + ((m & 1) << 3);
                int kseg = ks * 2 + (m >> 1);
                uint32_t addr = aBase + row * 128 +
                                (((uint32_t)(kseg ^ (row & 7))) << 4);
                LDSM_X4(a[mi], addr);
            }
            #pragma unroll
            for (int mi = 0; mi < 4; ++mi)
                #pragma unroll
                for (int ni = 0; ni < 8; ++ni)
                    MMA16816(acc[mi][ni], a[mi], b[ni]);
        }
    }
}

// ---------------------------------------------------------------------------
// Main kernel: fp32-faithful bf16 6-product GEMM + argmin.
// 4 warps, warp tile 64x64. A splits resident in smem, B double-buffered.
// Pairs: Bh x {Ah,Am,Al}, Bm x {Ah,Am}, Bl x {Ah}.
// score = ||e||^2/2 - z.e ; argmin, smallest-index tie-break.
// ---------------------------------------------------------------------------
__global__ void __launch_bounds__(128, 1)
argmin_mma_kernel(float* __restrict__ out_idx) {
    extern __shared__ char smem[];
    const int tid = threadIdx.x, lane = tid & 31, w = tid >> 5;
    const int row0 = blockIdx.x * BM;
    const int wm = (w >> 1) * 64, wn = (w & 1) * 64;
    const uint32_t sA = smem_u32(smem);
    const uint32_t sB = sA + A_BYTES;

    // ---- Prologue: all 12 A chunks + B step 0, one cp.async group ----
    {
        const char* gA = (const char*)g_zs + (size_t)row0 * 1536;
        for (int o = tid; o < 12288; o += 128) {
            int chunk = o >> 10;
            int rem = o & 1023;
            int row = rem >> 3, seg = rem & 7;
            uint32_t dst = sA + chunk * A_CHUNK_BYTES + row * 128 +
                           (((uint32_t)(seg ^ (row & 7))) << 4);
            cp16(dst, gA + (size_t)row * 1536 + chunk * 128 + seg * 16);
        }
        fill_B(sB, 0);
        CP_COMMIT();
    }

    float best[8];
    int   bidx[8];
    #pragma unroll
    for (int i = 0; i < 8; ++i) { best[i] = 3.4e38f; bidx[i] = 0; }

    int s = 0;
    for (int tile = 0; tile < NTILES; ++tile) {
        float acc[4][8][4];
        #pragma unroll
        for (int mi = 0; mi < 4; ++mi)
            #pragma unroll
            for (int ni = 0; ni < 8; ++ni)
                #pragma unroll
                for (int r = 0; r < 4; ++r) acc[mi][ni][r] = 0.f;

        // sbt = 0 (B = eh): partners Ah, Am, Al
        for (int kq = 0; kq < 4; ++kq, ++s) {
            CP_WAIT0();
            __syncthreads();
            if (s + 1 < NSTEPS) { fill_B(sB, s + 1); CP_COMMIT(); }
            chunk_pass<3>(sA, sB + (s & 1) * B_CHUNK_BYTES, kq, lane, acc, wm, wn);
        }
        // sbt = 1 (B = em): partners Ah, Am
        for (int kq = 0; kq < 4; ++kq, ++s) {
            CP_WAIT0();
            __syncthreads();
            if (s + 1 < NSTEPS) { fill_B(sB, s + 1); CP_COMMIT(); }
            chunk_pass<2>(sA, sB + (s & 1) * B_CHUNK_BYTES, kq, lane, acc, wm, wn);
        }
        // sbt = 2 (B = el): partner Ah
        for (int kq = 0; kq < 4; ++kq, ++s) {
            CP_WAIT0();
            __syncthreads();
            if (s + 1 < NSTEPS) { fill_B(sB, s + 1); CP_COMMIT(); }
            chunk_pass<1>(sA, sB + (s & 1) * B_CHUNK_BYTES, kq, lane, acc, wm, wn);
        }

        // ---- Epilogue: running argmin over this tile's 64x64 warp scores ----
        #pragma unroll
        for (int ni = 0; ni < 8; ++ni) {
            int c0 = tile * BN + wn + ni * 8 + ((lane & 3) << 1);
            float e0 = __ldg(&g_enorm[c0]);
            float e1 = __ldg(&g_enorm[c0 + 1]);
            #pragma unroll
            for (int mi = 0; mi < 4; ++mi) {
                float v0 = e0 - acc[mi][ni][0];
                if (v0 < best[mi * 2]) { best[mi * 2] = v0; bidx[mi * 2] = c0; }
                float v1 = e1 - acc[mi][ni][1];
                if (v1 < best[mi * 2]) { best[mi * 2] = v1; bidx[mi * 2] = c0 + 1; }
                float v2 = e0 - acc[mi][ni][2];
                if (v2 < best[mi * 2 + 1]) { best[mi * 2 + 1] = v2; bidx[mi * 2 + 1] = c0; }
                float v3 = e1 - acc[mi][ni][3];
                if (v3 < best[mi * 2 + 1]) { best[mi * 2 + 1] = v3; bidx[mi * 2 + 1] = c0 + 1; }
            }
        }
    }

    // ---- Cross-warp reduction (reuse B buffer region) ----
    __syncthreads();
    float* cv = (float*)(smem + A_BYTES);
    int*   ci = (int*)(smem + A_BYTES + 4096);
    int cs = ((w & 1) << 2) | (lane & 3);
    #pragma unroll
    for (int mi = 0; mi < 4; ++mi)
        #pragma unroll
        for (int h = 0; h < 2; ++h) {
            int row = wm + mi * 16 + (lane >> 2) + h * 8;
            cv[row * 8 + cs] = best[mi * 2 + h];
            ci[row * 8 + cs] = bidx[mi * 2 + h];
        }
    __syncthreads();

    {
        float bv = cv[tid * 8];
        int bi = ci[tid * 8];
        #pragma unroll
        for (int t = 1; t < 8; ++t) {
            float v = cv[tid * 8 + t];
            int ii = ci[tid * 8 + t];
            if (v < bv || (v == bv && ii < bi)) { bv = v; bi = ii; }
        }
        int row = row0 + tid;
        g_index[row] = bi;
        out_idx[row] = (float)bi;
        atomicAdd(&g_counts[bi], 1.0f);
    }
}

// ---------------------------------------------------------------------------
// Gather z_q + commitment-loss partials.
// ---------------------------------------------------------------------------
__global__ void gather_loss_kernel(const float* __restrict__ z,
                                   const float* __restrict__ e,
                                   float* __restrict__ out) {
    int i = blockIdx.x * blockDim.x + threadIdx.x;
    int row = i >> 6;
    int c4 = i & 63;
    int idx = g_index[row];
    float4 ev = ((const float4*)e)[(size_t)idx * 64 + c4];
    float4 zv = ((const float4*)z)[i];
    ((float4*)out)[i] = ev;
    float dx = ev.x - zv.x, dy = ev.y - zv.y;
    float dz = ev.z - zv.z, dw = ev.w - zv.w;
    float ls = dx * dx + dy * dy + dz * dz + dw * dw;

    __shared__ float red[32];
    #pragma unroll
    for (int o = 16; o; o >>= 1) ls += __shfl_xor_sync(0xffffffffu, ls, o);
    int l = threadIdx.x & 31, wq = threadIdx.x >> 5;
    if (l == 0) red[wq] = ls;
    __syncthreads();
    if (wq == 0) {
        float v = (l < ((int)blockDim.x >> 5)) ? red[l] : 0.f;
        #pragma unroll
        for (int o = 16; o; o >>= 1) v += __shfl_xor_sync(0xffffffffu, v, o);
        if (l == 0) atomicAdd(&g_loss_sum, v);
    }
}

// ---------------------------------------------------------------------------
// Finalize: loss scalar + perplexity.
// ---------------------------------------------------------------------------
__global__ void finalize_kernel(float* __restrict__ out) {
    const float invN = 1.0f / (float)NROWS;
    float s = 0.f;
    for (int k = threadIdx.x; k < KCODES; k += blockDim.x) {
        float p = g_counts[k] * invN;
        s += p * logf(p + 1e-10f);
    }
    __shared__ float red[32];
    #pragma unroll
    for (int o = 16; o; o >>= 1) s += __shfl_xor_sync(0xffffffffu, s, o);
    int l = threadIdx.x & 31, wq = threadIdx.x >> 5;
    if (l == 0) red[wq] = s;
    __syncthreads();
    if (wq == 0) {
        float v = (l < ((int)blockDim.x >> 5)) ? red[l] : 0.f;
        #pragma unroll
        for (int o = 16; o; o >>= 1) v += __shfl_xor_sync(0xffffffffu, v, o);
        if (l == 0) {
            const size_t NZ = (size_t)NROWS * DIM;
            out[NZ] = 0.25f * g_loss_sum / (float)NZ;
            out[NZ + 1 + NROWS] = expf(-v);
        }
    }
}

// ---------------------------------------------------------------------------
// Output layout (flattened tuple, float32):
//   [0, N*D) z_q_st | [N*D] loss | [N*D+1, +N) indices | [N*D+1+N] perplexity
// ---------------------------------------------------------------------------
extern "C" void kernel_launch(void* const* d_in, const int* in_sizes, int n_in,
                              void* d_out, int out_size) {
    const float* z = (const float*)d_in[0];
    const float* e = (const float*)d_in[1];
    float* out = (float*)d_out;

    cudaFuncSetAttribute(argmin_mma_kernel,
                         cudaFuncAttributeMaxDynamicSharedMemorySize, SMEM_BYTES);

    prep_z_kernel<<<(NROWS * 64) / 256, 256>>>(z);
    prep_e_kernel<<<KCODES * 32 / 256, 256>>>(e);
    argmin_mma_kernel<<<NROWS / BM, 128, SMEM_BYTES>>>(out + (size_t)NROWS * DIM + 1);
    gather_loss_kernel<<<(NROWS * (DIM / 4)) / 256, 256>>>(z, e, out);
    finalize_kernel<<<1, 256>>>(out);
}

// round 6
// speedup vs baseline: 5.1095x; 2.0656x over previous
#include <cuda_runtime.h>
#include <cuda_bf16.h>
#include <math.h>
#include <cstdint>

// ---------------------------------------------------------------------------
// Problem constants
// ---------------------------------------------------------------------------
#define DIM     256
#define KCODES  2048
#define NROWS   65536
#define BM      128            // z rows per CTA
#define BN      128            // codes per tile
#define NTILES  16             // KCODES / BN
#define NSTEPS_P 64            // 16 tiles * 4 chunks per pass

#define MARGIN  2.0f           // >> 2x worst realistic hh-score error
#define QCAP    3072

#define A_CHUNK_BYTES 16384    // 128 rows * 64 k * 2B
#define A_BYTES       65536    // 4 chunks (hh only)
#define B_CHUNK_BYTES 16384
// smem layout (bytes):
//   [0, 65536)        Ah (4 chunks)
//   [65536, 98304)    B double buffer
//   [98304, 98816)    rowlim[128] float
//   [98816, 99840)    rowbest[128] u64
//   [99840, 99968)    qcount (padded)
//   [99968, 112256)   queue[QCAP] u32   (pass-A reduction scratch overlaps here)
#define OFF_ROWLIM 98304
#define OFF_ROWBEST 98816
#define OFF_QCOUNT 99840
#define OFF_QUEUE  99968
#define SMEM_BYTES 112640

// ---------------------------------------------------------------------------
// Device scratch (static)
// ---------------------------------------------------------------------------
__device__ float g_enorm[KCODES];
__device__ int   g_index[NROWS];
__device__ float g_counts[KCODES];
__device__ float g_loss_sum;
__device__ __align__(16) __nv_bfloat16 g_es[KCODES * DIM];            // 1 MB (eh)
__device__ __align__(16) __nv_bfloat16 g_zs[(size_t)NROWS * DIM];     // 32 MB (zh)

// ---------------------------------------------------------------------------
// PTX helpers
// ---------------------------------------------------------------------------
__device__ __forceinline__ uint32_t smem_u32(const void* p) {
    uint32_t a;
    asm("{ .reg .u64 t; cvta.to.shared.u64 t, %1; cvt.u32.u64 %0, t; }"
        : "=r"(a) : "l"(p));
    return a;
}
__device__ __forceinline__ void cp16(uint32_t dst, const void* src) {
    asm volatile("cp.async.cg.shared.global [%0], [%1], 16;" :: "r"(dst), "l"(src));
}
#define CP_COMMIT() asm volatile("cp.async.commit_group;" ::: "memory")
#define CP_WAIT0()  asm volatile("cp.async.wait_group 0;" ::: "memory")

#define LDSM_X4(r, addr) \
    asm volatile("ldmatrix.sync.aligned.m8n8.x4.shared.b16 {%0,%1,%2,%3}, [%4];" \
        : "=r"((r)[0]), "=r"((r)[1]), "=r"((r)[2]), "=r"((r)[3]) : "r"(addr))

#define LDSM_X4B(r0, r1, r2, r3, addr) \
    asm volatile("ldmatrix.sync.aligned.m8n8.x4.shared.b16 {%0,%1,%2,%3}, [%4];" \
        : "=r"(r0), "=r"(r1), "=r"(r2), "=r"(r3) : "r"(addr))

#define MMA16816(d, a, b) \
    asm volatile("mma.sync.aligned.m16n8k16.row.col.f32.bf16.bf16.f32 " \
        "{%0,%1,%2,%3}, {%4,%5,%6,%7}, {%8,%9}, {%0,%1,%2,%3};" \
        : "+f"((d)[0]), "+f"((d)[1]), "+f"((d)[2]), "+f"((d)[3]) \
        : "r"((a)[0]), "r"((a)[1]), "r"((a)[2]), "r"((a)[3]), \
          "r"((b)[0]), "r"((b)[1]))

__device__ __forceinline__ uint32_t pack2h(float a, float b) {
    __nv_bfloat16 h0 = __float2bfloat16(a), h1 = __float2bfloat16(b);
    return ((uint32_t)__bfloat16_as_ushort(h1) << 16) |
           (uint32_t)__bfloat16_as_ushort(h0);
}

// ---------------------------------------------------------------------------
// Prep 1: z -> g_zs (bf16 hi part). One thread per float4.
// ---------------------------------------------------------------------------
__global__ void prep_z_kernel(const float* __restrict__ z) {
    int i = blockIdx.x * blockDim.x + threadIdx.x;   // 0 .. NROWS*64-1
    float4 v = ((const float4*)z)[i];
    ((uint2*)g_zs)[i] = make_uint2(pack2h(v.x, v.y), pack2h(v.z, v.w));
}

// ---------------------------------------------------------------------------
// Prep 2: e -> g_es (bf16 hi) + half-norms + zero scratch. One warp per code.
// ---------------------------------------------------------------------------
__global__ void prep_e_kernel(const float* __restrict__ e) {
    int t = blockIdx.x * blockDim.x + threadIdx.x;
    int w = t >> 5, l = t & 31;
    if (w < KCODES) {
        const float4* row = (const float4*)(e + (size_t)w * DIM);
        float4 a = row[2 * l], b = row[2 * l + 1];
        uint32_t ph[4] = {pack2h(a.x, a.y), pack2h(a.z, a.w),
                          pack2h(b.x, b.y), pack2h(b.z, b.w)};
        ((uint4*)g_es)[(size_t)w * 32 + l] = *(uint4*)ph;
        float s = a.x*a.x + a.y*a.y + a.z*a.z + a.w*a.w
                + b.x*b.x + b.y*b.y + b.z*b.z + b.w*b.w;
        #pragma unroll
        for (int o = 16; o; o >>= 1) s += __shfl_xor_sync(0xffffffffu, s, o);
        if (l == 0) { g_enorm[w] = 0.5f * s; g_counts[w] = 0.f; }
    }
    if (t == 0) g_loss_sum = 0.f;
}

// ---------------------------------------------------------------------------
// B tile fill: 128 codes x 64 k of eh into swizzled smem. step: tile*4+chunk.
// ---------------------------------------------------------------------------
__device__ __forceinline__ void fill_B(uint32_t sB, int step) {
    int tile = step >> 2, chunk = step & 3, buf = step & 1;
    const char* src0 = (const char*)g_es + (size_t)tile * BN * 512 + chunk * 128;
    uint32_t d0 = sB + buf * B_CHUNK_BYTES;
    #pragma unroll
    for (int o = 0; o < 8; ++o) {
        int idx = threadIdx.x + o * 128;             // 0..1023
        int row = idx >> 3, seg = idx & 7;
        uint32_t dst = d0 + row * 128 + (((uint32_t)(seg ^ (row & 7))) << 4);
        cp16(dst, src0 + (size_t)row * 512 + seg * 16);
    }
}

// ---------------------------------------------------------------------------
// One hh chunk: 4 ks-steps of (8 LDSM.x4 + 32 MMA). Maps proven in R5.
// ---------------------------------------------------------------------------
__device__ __forceinline__ void chunk_mma(
    uint32_t aBase, uint32_t bBase, int lane,
    float (&acc)[4][8][4], int wm, int wn)
{
    const int m = lane >> 3, r8 = lane & 7;
    #pragma unroll
    for (int ks = 0; ks < 4; ++ks) {
        uint32_t b[8][2];
        #pragma unroll
        for (int nb = 0; nb < 4; ++nb) {
            int code = wn + nb * 16 + ((m >> 1) << 3) + r8;
            int kseg = ks * 2 + (m & 1);
            uint32_t addr = bBase + code * 128 +
                            (((uint32_t)(kseg ^ (code & 7))) << 4);
            LDSM_X4B(b[2 * nb][0], b[2 * nb][1],
                     b[2 * nb + 1][0], b[2 * nb + 1][1], addr);
        }
        uint32_t a[4][4];
        #pragma unroll
        for (int mi = 0; mi < 4; ++mi) {
            int row = wm + mi * 16 + r8 + ((m & 1) << 3);
            int kseg = ks * 2 + (m >> 1);
            uint32_t addr = aBase + row * 128 +
                            (((uint32_t)(kseg ^ (row & 7))) << 4);
            LDSM_X4(a[mi], addr);
        }
        #pragma unroll
        for (int mi = 0; mi < 4; ++mi)
            #pragma unroll
            for (int ni = 0; ni < 8; ++ni)
                MMA16816(acc[mi][ni], a[mi], b[ni]);
    }
}

// ---------------------------------------------------------------------------
// Main kernel: two-pass hh GEMM + margin-gated exact fp32 rescore.
// ---------------------------------------------------------------------------
__global__ void __launch_bounds__(128, 2)
argmin_mma_kernel(const float* __restrict__ z, const float* __restrict__ e,
                  float* __restrict__ out_idx) {
    extern __shared__ char smem[];
    const int tid = threadIdx.x, lane = tid & 31, w = tid >> 5;
    const int row0 = blockIdx.x * BM;
    const int wm = (w >> 1) * 64, wn = (w & 1) * 64;
    const uint32_t sA = smem_u32(smem);
    const uint32_t sB = sA + A_BYTES;
    float* rowlim = (float*)(smem + OFF_ROWLIM);
    unsigned long long* rowbest = (unsigned long long*)(smem + OFF_ROWBEST);
    int* qcount = (int*)(smem + OFF_QCOUNT);
    uint32_t* queue = (uint32_t*)(smem + OFF_QUEUE);
    float* cv = (float*)(smem + OFF_QUEUE);   // pass-A reduction scratch

    rowbest[tid] = ~0ull;
    if (tid == 0) *qcount = 0;

    // ---- Prologue: Ah (4 chunks) + B step 0 ----
    {
        const char* gA = (const char*)g_zs + (size_t)row0 * 512;
        for (int o = tid; o < 4096; o += 128) {
            int chunk = o >> 10, rem = o & 1023;
            int row = rem >> 3, seg = rem & 7;
            uint32_t dst = sA + chunk * A_CHUNK_BYTES + row * 128 +
                           (((uint32_t)(seg ^ (row & 7))) << 4);
            cp16(dst, gA + (size_t)row * 512 + chunk * 128 + seg * 16);
        }
        fill_B(sB, 0);
        CP_COMMIT();
    }

    // =========================== PASS A: find min ==========================
    float best[8];
    #pragma unroll
    for (int i = 0; i < 8; ++i) best[i] = 3.4e38f;

    {
        int s = 0;
        for (int tile = 0; tile < NTILES; ++tile) {
            float acc[4][8][4];
            #pragma unroll
            for (int mi = 0; mi < 4; ++mi)
                #pragma unroll
                for (int ni = 0; ni < 8; ++ni)
                    #pragma unroll
                    for (int r = 0; r < 4; ++r) acc[mi][ni][r] = 0.f;
            for (int chunk = 0; chunk < 4; ++chunk, ++s) {
                CP_WAIT0();
                __syncthreads();
                if (s + 1 < NSTEPS_P) { fill_B(sB, s + 1); CP_COMMIT(); }
                chunk_mma(sA + chunk * A_CHUNK_BYTES,
                          sB + (s & 1) * B_CHUNK_BYTES, lane, acc, wm, wn);
            }
            #pragma unroll
            for (int ni = 0; ni < 8; ++ni) {
                int c0 = tile * BN + wn + ni * 8 + ((lane & 3) << 1);
                float e0 = __ldg(&g_enorm[c0]);
                float e1 = __ldg(&g_enorm[c0 + 1]);
                #pragma unroll
                for (int mi = 0; mi < 4; ++mi) {
                    best[mi*2]   = fminf(best[mi*2],   fminf(e0 - acc[mi][ni][0], e1 - acc[mi][ni][1]));
                    best[mi*2+1] = fminf(best[mi*2+1], fminf(e0 - acc[mi][ni][2], e1 - acc[mi][ni][3]));
                }
            }
        }
    }

    // ---- Cross-warp min reduction -> rowlim = min + MARGIN ----
    __syncthreads();
    {
        int cs = ((w & 1) << 2) | (lane & 3);
        #pragma unroll
        for (int mi = 0; mi < 4; ++mi)
            #pragma unroll
            for (int h = 0; h < 2; ++h) {
                int row = wm + mi * 16 + (lane >> 2) + h * 8;
                cv[row * 8 + cs] = best[mi * 2 + h];
            }
    }
    __syncthreads();
    {
        float bv = cv[tid * 8];
        #pragma unroll
        for (int t = 1; t < 8; ++t) bv = fminf(bv, cv[tid * 8 + t]);
        rowlim[tid] = bv + MARGIN;
    }
    __syncthreads();

    float rl[8];
    #pragma unroll
    for (int mi = 0; mi < 4; ++mi)
        #pragma unroll
        for (int h = 0; h < 2; ++h)
            rl[mi * 2 + h] = rowlim[wm + mi * 16 + (lane >> 2) + h * 8];

    // ======================= PASS B: collect candidates ====================
    fill_B(sB, 0);
    CP_COMMIT();
    {
        int s = 0;
        for (int tile = 0; tile < NTILES; ++tile) {
            float acc[4][8][4];
            #pragma unroll
            for (int mi = 0; mi < 4; ++mi)
                #pragma unroll
                for (int ni = 0; ni < 8; ++ni)
                    #pragma unroll
                    for (int r = 0; r < 4; ++r) acc[mi][ni][r] = 0.f;
            for (int chunk = 0; chunk < 4; ++chunk, ++s) {
                CP_WAIT0();
                __syncthreads();
                if (s + 1 < NSTEPS_P) { fill_B(sB, s + 1); CP_COMMIT(); }
                chunk_mma(sA + chunk * A_CHUNK_BYTES,
                          sB + (s & 1) * B_CHUNK_BYTES, lane, acc, wm, wn);
            }
            #pragma unroll
            for (int ni = 0; ni < 8; ++ni) {
                int c0 = tile * BN + wn + ni * 8 + ((lane & 3) << 1);
                float e0 = __ldg(&g_enorm[c0]);
                float e1 = __ldg(&g_enorm[c0 + 1]);
                #pragma unroll
                for (int mi = 0; mi < 4; ++mi) {
                    #pragma unroll
                    for (int h = 0; h < 2; ++h) {
                        int rloc = wm + mi * 16 + (lane >> 2) + h * 8;
                        float v0 = e0 - acc[mi][ni][2 * h];
                        float v1 = e1 - acc[mi][ni][2 * h + 1];
                        if (v0 < rl[mi * 2 + h]) {
                            int qi = atomicAdd(qcount, 1);
                            if (qi < QCAP) queue[qi] = ((uint32_t)rloc << 11) | (uint32_t)c0;
                        }
                        if (v1 < rl[mi * 2 + h]) {
                            int qi = atomicAdd(qcount, 1);
                            if (qi < QCAP) queue[qi] = ((uint32_t)rloc << 11) | (uint32_t)(c0 + 1);
                        }
                    }
                }
            }
        }
    }

    // ======================= Exact fp32 rescore ============================
    __syncthreads();
    int qn = *qcount; if (qn > QCAP) qn = QCAP;
    for (int q = tid; q < qn; q += 128) {
        uint32_t ent = queue[q];
        int rloc = (int)(ent >> 11);
        int code = (int)(ent & 2047u);
        const float4* zr = (const float4*)(z + (size_t)(row0 + rloc) * DIM);
        const float4* er = (const float4*)(e + (size_t)code * DIM);
        float a0 = 0.f, a1 = 0.f, a2 = 0.f, a3 = 0.f;
        #pragma unroll 8
        for (int i = 0; i < 64; ++i) {
            float4 zv = __ldg(&zr[i]);
            float4 ev = __ldg(&er[i]);
            a0 += zv.x * ev.x; a1 += zv.y * ev.y;
            a2 += zv.z * ev.z; a3 += zv.w * ev.w;
        }
        float sc = __ldg(&g_enorm[code]) - ((a0 + a1) + (a2 + a3));
        uint32_t k = __float_as_uint(sc);
        k = (k & 0x80000000u) ? ~k : (k | 0x80000000u);
        unsigned long long key = ((unsigned long long)k << 32) | (uint32_t)code;
        atomicMin(&rowbest[rloc], key);
    }
    __syncthreads();

    // ---- Outputs: each thread owns one row ----
    {
        int bi = (int)(rowbest[tid] & 0xFFFFFFFFull);
        int row = row0 + tid;
        g_index[row] = bi;
        out_idx[row] = (float)bi;
        atomicAdd(&g_counts[bi], 1.0f);
    }
}

// ---------------------------------------------------------------------------
// Gather z_q + commitment-loss partials.
// ---------------------------------------------------------------------------
__global__ void gather_loss_kernel(const float* __restrict__ z,
                                   const float* __restrict__ e,
                                   float* __restrict__ out) {
    int i = blockIdx.x * blockDim.x + threadIdx.x;
    int row = i >> 6;
    int c4 = i & 63;
    int idx = g_index[row];
    float4 ev = ((const float4*)e)[(size_t)idx * 64 + c4];
    float4 zv = ((const float4*)z)[i];
    ((float4*)out)[i] = ev;
    float dx = ev.x - zv.x, dy = ev.y - zv.y;
    float dz = ev.z - zv.z, dw = ev.w - zv.w;
    float ls = dx * dx + dy * dy + dz * dz + dw * dw;

    __shared__ float red[32];
    #pragma unroll
    for (int o = 16; o; o >>= 1) ls += __shfl_xor_sync(0xffffffffu, ls, o);
    int l = threadIdx.x & 31, wq = threadIdx.x >> 5;
    if (l == 0) red[wq] = ls;
    __syncthreads();
    if (wq == 0) {
        float v = (l < ((int)blockDim.x >> 5)) ? red[l] : 0.f;
        #pragma unroll
        for (int o = 16; o; o >>= 1) v += __shfl_xor_sync(0xffffffffu, v, o);
        if (l == 0) atomicAdd(&g_loss_sum, v);
    }
}

// ---------------------------------------------------------------------------
// Finalize: loss scalar + perplexity.
// ---------------------------------------------------------------------------
__global__ void finalize_kernel(float* __restrict__ out) {
    const float invN = 1.0f / (float)NROWS;
    float s = 0.f;
    for (int k = threadIdx.x; k < KCODES; k += blockDim.x) {
        float p = g_counts[k] * invN;
        s += p * logf(p + 1e-10f);
    }
    __shared__ float red[32];
    #pragma unroll
    for (int o = 16; o; o >>= 1) s += __shfl_xor_sync(0xffffffffu, s, o);
    int l = threadIdx.x & 31, wq = threadIdx.x >> 5;
    if (l == 0) red[wq] = s;
    __syncthreads();
    if (wq == 0) {
        float v = (l < ((int)blockDim.x >> 5)) ? red[l] : 0.f;
        #pragma unroll
        for (int o = 16; o; o >>= 1) v += __shfl_xor_sync(0xffffffffu, v, o);
        if (l == 0) {
            const size_t NZ = (size_t)NROWS * DIM;
            out[NZ] = 0.25f * g_loss_sum / (float)NZ;
            out[NZ + 1 + NROWS] = expf(-v);
        }
    }
}

// ---------------------------------------------------------------------------
// Output layout (flattened tuple, float32):
//   [0, N*D) z_q_st | [N*D] loss | [N*D+1, +N) indices | [N*D+1+N] perplexity
// ---------------------------------------------------------------------------
extern "C" void kernel_launch(void* const* d_in, const int* in_sizes, int n_in,
                              void* d_out, int out_size) {
    const float* z = (const float*)d_in[0];
    const float* e = (const float*)d_in[1];
    float* out = (float*)d_out;

    cudaFuncSetAttribute(argmin_mma_kernel,
                         cudaFuncAttributeMaxDynamicSharedMemorySize, SMEM_BYTES);

    prep_z_kernel<<<(NROWS * 64) / 256, 256>>>(z);
    prep_e_kernel<<<KCODES * 32 / 256, 256>>>(e);
    argmin_mma_kernel<<<NROWS / BM, 128, SMEM_BYTES>>>(
        z, e, out + (size_t)NROWS * DIM + 1);
    gather_loss_kernel<<<(NROWS * (DIM / 4)) / 256, 256>>>(z, e, out);
    finalize_kernel<<<1, 256>>>(out);
}